// round 1
// baseline (speedup 1.0000x reference)
#include <cuda_runtime.h>
#include <cuda_bf16.h>
#include <cstdint>

#define NUM_USERS 100000
#define NUM_ITEMS 50000
#define N_NODES   150000
#define EMB       64
#define BATCH     4096

// Static scratch (allocation-free): 4 x 38.4 MB
__device__ float g_cur[(size_t)N_NODES * EMB];
__device__ float g_bufA[(size_t)N_NODES * EMB];
__device__ float g_bufB[(size_t)N_NODES * EMB];
__device__ float g_acc[(size_t)N_NODES * EMB];

// ---------------------------------------------------------------------------
// init: cur = acc = concat(user_emb, item_emb); zero bufA (layer-1 target)
// ---------------------------------------------------------------------------
__global__ void init_kernel(const float4* __restrict__ uemb,
                            const float4* __restrict__ iemb,
                            float4* __restrict__ cur,
                            float4* __restrict__ acc,
                            float4* __restrict__ zbuf)
{
    const int n4      = N_NODES * (EMB / 4);          // 2,400,000
    const int n4_user = NUM_USERS * (EMB / 4);        // 1,600,000
    int i = blockIdx.x * blockDim.x + threadIdx.x;
    if (i >= n4) return;
    float4 v = (i < n4_user) ? uemb[i] : iemb[i - n4_user];
    cur[i] = v;
    acc[i] = v;
    zbuf[i] = make_float4(0.f, 0.f, 0.f, 0.f);
}

// ---------------------------------------------------------------------------
// SpMM (COO): half-warp per edge, float4 lanes, vector reduction atomics
// ---------------------------------------------------------------------------
__global__ void spmm_kernel(const int*   __restrict__ rows,
                            const int*   __restrict__ cols,
                            const float* __restrict__ vals,
                            const float* __restrict__ src,
                            float*       __restrict__ dst,
                            int n_edges)
{
    int t = blockIdx.x * blockDim.x + threadIdx.x;
    int e = t >> 4;          // edge index  (16 lanes per edge)
    int l = t & 15;          // lane within edge: covers 64 floats as 16 x float4
    if (e >= n_edges) return;

    int   row = __ldg(rows + e);
    int   col = __ldg(cols + e);
    float v   = __ldg(vals + e);

    const float4* s = reinterpret_cast<const float4*>(src + (size_t)col * EMB);
    float4 x = __ldg(s + l);
    x.x *= v; x.y *= v; x.z *= v; x.w *= v;

    float* d = dst + (size_t)row * EMB + l * 4;
    asm volatile("red.global.add.v4.f32 [%0], {%1, %2, %3, %4};"
                 :: "l"(d), "f"(x.x), "f"(x.y), "f"(x.z), "f"(x.w)
                 : "memory");
}

// ---------------------------------------------------------------------------
// acc += src;  zbuf = 0   (fused so each layer boundary is one pass)
// ---------------------------------------------------------------------------
__global__ void add_zero_kernel(float4* __restrict__ acc,
                                const float4* __restrict__ src,
                                float4* __restrict__ zbuf)
{
    const int n4 = N_NODES * (EMB / 4);
    int i = blockIdx.x * blockDim.x + threadIdx.x;
    if (i >= n4) return;
    float4 a = acc[i];
    float4 s = src[i];
    a.x += s.x; a.y += s.y; a.z += s.z; a.w += s.w;
    acc[i] = a;
    zbuf[i] = make_float4(0.f, 0.f, 0.f, 0.f);
}

__global__ void add_kernel(float4* __restrict__ acc,
                           const float4* __restrict__ src)
{
    const int n4 = N_NODES * (EMB / 4);
    int i = blockIdx.x * blockDim.x + threadIdx.x;
    if (i >= n4) return;
    float4 a = acc[i];
    float4 s = src[i];
    a.x += s.x; a.y += s.y; a.z += s.z; a.w += s.w;
    acc[i] = a;
}

// ---------------------------------------------------------------------------
// scoring: one warp per batch element; out[0:B)=pos, out[B:2B)=neg
// final = acc/4 -> dot(u,i) = dot(acc_u, acc_i) / 16
// ---------------------------------------------------------------------------
__global__ void score_kernel(const int* __restrict__ users,
                             const int* __restrict__ pos_items,
                             const int* __restrict__ neg_items,
                             const float* __restrict__ acc,
                             float* __restrict__ out,
                             int batch)
{
    int w = (blockIdx.x * blockDim.x + threadIdx.x) >> 5;
    int l = threadIdx.x & 31;
    if (w >= batch) return;

    int urow = __ldg(users + w);
    int prow = NUM_USERS + __ldg(pos_items + w);
    int nrow = NUM_USERS + __ldg(neg_items + w);

    const float2* base = reinterpret_cast<const float2*>(acc);
    float2 u = __ldg(base + (size_t)urow * (EMB / 2) + l);
    float2 p = __ldg(base + (size_t)prow * (EMB / 2) + l);
    float2 q = __ldg(base + (size_t)nrow * (EMB / 2) + l);

    float ps = u.x * p.x + u.y * p.y;
    float ns = u.x * q.x + u.y * q.y;
    #pragma unroll
    for (int o = 16; o; o >>= 1) {
        ps += __shfl_xor_sync(0xFFFFFFFFu, ps, o);
        ns += __shfl_xor_sync(0xFFFFFFFFu, ns, o);
    }
    if (l == 0) {
        out[w]         = ps * (1.0f / 16.0f);
        out[batch + w] = ns * (1.0f / 16.0f);
    }
}

// ---------------------------------------------------------------------------
extern "C" void kernel_launch(void* const* d_in, const int* in_sizes, int n_in,
                              void* d_out, int out_size)
{
    const int*   users = (const int*)  d_in[0];
    const int*   pos   = (const int*)  d_in[1];
    const int*   neg   = (const int*)  d_in[2];
    const int*   rows  = (const int*)  d_in[3];
    const int*   cols  = (const int*)  d_in[4];
    const float* vals  = (const float*)d_in[5];
    const float* uemb  = (const float*)d_in[6];
    const float* iemb  = (const float*)d_in[7];
    float* out = (float*)d_out;

    const int n_edges = in_sizes[3];
    const int batch   = in_sizes[0];

    float *cur, *bufA, *bufB, *acc;
    cudaGetSymbolAddress((void**)&cur,  g_cur);
    cudaGetSymbolAddress((void**)&bufA, g_bufA);
    cudaGetSymbolAddress((void**)&bufB, g_bufB);
    cudaGetSymbolAddress((void**)&acc,  g_acc);

    const int n4 = N_NODES * (EMB / 4);
    const int TB = 256;
    const int grid_n4   = (n4 + TB - 1) / TB;
    const long long spmm_threads = (long long)n_edges * 16;
    const int grid_spmm = (int)((spmm_threads + TB - 1) / TB);

    // init: cur=acc=emb, bufA=0
    init_kernel<<<grid_n4, TB>>>((const float4*)uemb, (const float4*)iemb,
                                 (float4*)cur, (float4*)acc, (float4*)bufA);

    // layer 1: bufA <- A*cur ; acc += bufA ; zero bufB
    spmm_kernel<<<grid_spmm, TB>>>(rows, cols, vals, cur, bufA, n_edges);
    add_zero_kernel<<<grid_n4, TB>>>((float4*)acc, (const float4*)bufA, (float4*)bufB);

    // layer 2: bufB <- A*bufA ; acc += bufB ; zero cur (reused as layer-3 target)
    spmm_kernel<<<grid_spmm, TB>>>(rows, cols, vals, bufA, bufB, n_edges);
    add_zero_kernel<<<grid_n4, TB>>>((float4*)acc, (const float4*)bufB, (float4*)cur);

    // layer 3: cur <- A*bufB ; acc += cur
    spmm_kernel<<<grid_spmm, TB>>>(rows, cols, vals, bufB, cur, n_edges);
    add_kernel<<<grid_n4, TB>>>((float4*)acc, (const float4*)cur);

    // scores
    const int score_warps_per_block = TB / 32;
    const int grid_score = (batch + score_warps_per_block - 1) / score_warps_per_block;
    score_kernel<<<grid_score, TB>>>(users, pos, neg, acc, out, batch);
}

// round 2
// speedup vs baseline: 2.2502x; 2.2502x over previous
#include <cuda_runtime.h>
#include <cuda_bf16.h>
#include <cstdint>

#define NUM_USERS 100000
#define NUM_ITEMS 50000
#define N_NODES   150000
#define EMB       64
#define BATCH     4096
#define MAX_EDGES 4800000

#define SCAN_BS   1024
#define SCAN_NB   ((N_NODES + SCAN_BS - 1) / SCAN_BS)   // 147

// ---- static scratch (allocation-free) ----
__device__ float g_cur [(size_t)N_NODES * EMB];
__device__ float g_bufA[(size_t)N_NODES * EMB];
__device__ float g_bufB[(size_t)N_NODES * EMB];
__device__ float g_acc [(size_t)N_NODES * EMB];
__device__ int2  g_edges[MAX_EDGES];        // {col, val_bits} sorted by row
__device__ int   g_count[N_NODES];
__device__ int   g_rowptr[N_NODES + 1];
__device__ int   g_off[N_NODES];
__device__ int   g_blocksum[SCAN_NB];
__device__ int   g_blockoff[SCAN_NB];

// ---------------------------------------------------------------------------
// init: cur = acc = concat(user_emb, item_emb); zero row counters
// ---------------------------------------------------------------------------
__global__ void init_kernel(const float4* __restrict__ uemb,
                            const float4* __restrict__ iemb,
                            float4* __restrict__ cur,
                            float4* __restrict__ acc)
{
    const int n4      = N_NODES * (EMB / 4);
    const int n4_user = NUM_USERS * (EMB / 4);
    int i = blockIdx.x * blockDim.x + threadIdx.x;
    if (i < N_NODES) g_count[i] = 0;
    if (i >= n4) return;
    float4 v = (i < n4_user) ? __ldg(uemb + i) : __ldg(iemb + i - n4_user);
    cur[i] = v;
    acc[i] = v;
}

// ---------------------------------------------------------------------------
// COO -> CSR: histogram, 3-step scan, scatter
// ---------------------------------------------------------------------------
__global__ void hist_kernel(const int* __restrict__ rows, int n)
{
    int i = blockIdx.x * blockDim.x + threadIdx.x;
    if (i < n) atomicAdd(&g_count[rows[i]], 1);
}

__global__ void scan1_kernel()   // per-block sums of g_count
{
    int idx = blockIdx.x * SCAN_BS + threadIdx.x;
    int c = (idx < N_NODES) ? g_count[idx] : 0;
    int lane = threadIdx.x & 31, wid = threadIdx.x >> 5;
    #pragma unroll
    for (int o = 16; o; o >>= 1) c += __shfl_down_sync(0xFFFFFFFFu, c, o);
    __shared__ int ws[32];
    if (lane == 0) ws[wid] = c;
    __syncthreads();
    if (wid == 0) {
        c = ws[lane];
        #pragma unroll
        for (int o = 16; o; o >>= 1) c += __shfl_down_sync(0xFFFFFFFFu, c, o);
        if (lane == 0) g_blocksum[blockIdx.x] = c;
    }
}

__global__ void scan2_kernel(int n_edges)  // exclusive scan of block sums
{
    __shared__ int sh[SCAN_NB];
    int t = threadIdx.x;
    for (int i = t; i < SCAN_NB; i += blockDim.x) sh[i] = g_blocksum[i];
    __syncthreads();
    if (t == 0) {
        int run = 0;
        for (int i = 0; i < SCAN_NB; i++) { int v = sh[i]; sh[i] = run; run += v; }
        g_rowptr[N_NODES] = n_edges;
    }
    __syncthreads();
    for (int i = t; i < SCAN_NB; i += blockDim.x) g_blockoff[i] = sh[i];
}

__global__ void scan3_kernel()   // block-local exclusive scan + offset
{
    int idx = blockIdx.x * SCAN_BS + threadIdx.x;
    int c = (idx < N_NODES) ? g_count[idx] : 0;
    int lane = threadIdx.x & 31, wid = threadIdx.x >> 5;
    int v = c;
    #pragma unroll
    for (int o = 1; o < 32; o <<= 1) {
        int t = __shfl_up_sync(0xFFFFFFFFu, v, o);
        if (lane >= o) v += t;
    }
    __shared__ int ws[32];
    if (lane == 31) ws[wid] = v;
    __syncthreads();
    if (wid == 0) {
        int orig = ws[lane];
        int s = orig;
        #pragma unroll
        for (int o = 1; o < 32; o <<= 1) {
            int t = __shfl_up_sync(0xFFFFFFFFu, s, o);
            if (lane >= o) s += t;
        }
        ws[lane] = s - orig;   // exclusive warp offsets
    }
    __syncthreads();
    int excl = (v - c) + ws[wid] + g_blockoff[blockIdx.x];
    if (idx < N_NODES) { g_rowptr[idx] = excl; g_off[idx] = excl; }
}

__global__ void scatter_kernel(const int* __restrict__ rows,
                               const int* __restrict__ cols,
                               const float* __restrict__ vals, int n)
{
    int i = blockIdx.x * blockDim.x + threadIdx.x;
    if (i >= n) return;
    int row = rows[i];
    int pos = atomicAdd(&g_off[row], 1);
    g_edges[pos] = make_int2(cols[i], __float_as_int(vals[i]));
}

// ---------------------------------------------------------------------------
// CSR SpMM: 16 lanes per destination row, register accumulator, no atomics.
// dst[row] = sum_e val_e * src[col_e];  acc[row] += dst[row]  (fused)
// ---------------------------------------------------------------------------
__global__ void spmm_csr_kernel(const float4* __restrict__ src,
                                float4* __restrict__ dst,
                                float4* __restrict__ acc)
{
    int g = (blockIdx.x * blockDim.x + threadIdx.x) >> 4;  // row
    int l = threadIdx.x & 15;                              // feature float4 slot
    unsigned gmask = 0xFFFFu << (threadIdx.x & 16);        // this half-warp
    // grid sized exactly: N_NODES groups, no stragglers
    int start = __ldg(&g_rowptr[g]);
    int end   = __ldg(&g_rowptr[g + 1]);

    float4 a = make_float4(0.f, 0.f, 0.f, 0.f);

    int base = start;
    // full 16-edge batches: coalesced edge prefetch + fully unrolled gathers
    for (; base + 16 <= end; base += 16) {
        int2 e = __ldg(&g_edges[base + l]);
        #pragma unroll
        for (int k = 0; k < 16; k++) {
            int   col = __shfl_sync(gmask, e.x, k, 16);
            float v   = __int_as_float(__shfl_sync(gmask, e.y, k, 16));
            float4 x  = __ldg(src + (size_t)col * 16 + l);
            a.x = fmaf(v, x.x, a.x);
            a.y = fmaf(v, x.y, a.y);
            a.z = fmaf(v, x.z, a.z);
            a.w = fmaf(v, x.w, a.w);
        }
    }
    // remainder
    int rem = end - base;
    if (rem > 0) {
        int2 e = (l < rem) ? __ldg(&g_edges[base + l]) : make_int2(0, 0);
        for (int k = 0; k < rem; k++) {
            int   col = __shfl_sync(gmask, e.x, k, 16);
            float v   = __int_as_float(__shfl_sync(gmask, e.y, k, 16));
            float4 x  = __ldg(src + (size_t)col * 16 + l);
            a.x = fmaf(v, x.x, a.x);
            a.y = fmaf(v, x.y, a.y);
            a.z = fmaf(v, x.z, a.z);
            a.w = fmaf(v, x.w, a.w);
        }
    }

    size_t o = (size_t)g * 16 + l;
    dst[o] = a;
    float4 ac = acc[o];
    ac.x += a.x; ac.y += a.y; ac.z += a.z; ac.w += a.w;
    acc[o] = ac;
}

// ---------------------------------------------------------------------------
// scoring: one warp per batch element; out[0:B)=pos, out[B:2B)=neg
// final = acc/4 -> score = dot(acc_u, acc_i) / 16
// ---------------------------------------------------------------------------
__global__ void score_kernel(const int* __restrict__ users,
                             const int* __restrict__ pos_items,
                             const int* __restrict__ neg_items,
                             const float* __restrict__ acc,
                             float* __restrict__ out,
                             int batch)
{
    int w = (blockIdx.x * blockDim.x + threadIdx.x) >> 5;
    int l = threadIdx.x & 31;
    if (w >= batch) return;

    int urow = __ldg(users + w);
    int prow = NUM_USERS + __ldg(pos_items + w);
    int nrow = NUM_USERS + __ldg(neg_items + w);

    const float2* base = reinterpret_cast<const float2*>(acc);
    float2 u = __ldg(base + (size_t)urow * (EMB / 2) + l);
    float2 p = __ldg(base + (size_t)prow * (EMB / 2) + l);
    float2 q = __ldg(base + (size_t)nrow * (EMB / 2) + l);

    float ps = u.x * p.x + u.y * p.y;
    float ns = u.x * q.x + u.y * q.y;
    #pragma unroll
    for (int o = 16; o; o >>= 1) {
        ps += __shfl_xor_sync(0xFFFFFFFFu, ps, o);
        ns += __shfl_xor_sync(0xFFFFFFFFu, ns, o);
    }
    if (l == 0) {
        out[w]         = ps * (1.0f / 16.0f);
        out[batch + w] = ns * (1.0f / 16.0f);
    }
}

// ---------------------------------------------------------------------------
extern "C" void kernel_launch(void* const* d_in, const int* in_sizes, int n_in,
                              void* d_out, int out_size)
{
    const int*   users = (const int*)  d_in[0];
    const int*   pos   = (const int*)  d_in[1];
    const int*   neg   = (const int*)  d_in[2];
    const int*   rows  = (const int*)  d_in[3];
    const int*   cols  = (const int*)  d_in[4];
    const float* vals  = (const float*)d_in[5];
    const float* uemb  = (const float*)d_in[6];
    const float* iemb  = (const float*)d_in[7];
    float* out = (float*)d_out;

    const int n_edges = in_sizes[3];
    const int batch   = in_sizes[0];

    float *cur, *bufA, *bufB, *acc;
    cudaGetSymbolAddress((void**)&cur,  g_cur);
    cudaGetSymbolAddress((void**)&bufA, g_bufA);
    cudaGetSymbolAddress((void**)&bufB, g_bufB);
    cudaGetSymbolAddress((void**)&acc,  g_acc);

    const int n4 = N_NODES * (EMB / 4);
    const int TB = 256;
    const int grid_n4   = (n4 + TB - 1) / TB;
    const int grid_edge = (n_edges + TB - 1) / TB;
    const int grid_spmm = (N_NODES * 16) / TB;          // exact: 9375

    // emb -> cur, acc; zero counters
    init_kernel<<<grid_n4, TB>>>((const float4*)uemb, (const float4*)iemb,
                                 (float4*)cur, (float4*)acc);

    // COO -> CSR
    hist_kernel<<<grid_edge, TB>>>(rows, n_edges);
    scan1_kernel<<<SCAN_NB, SCAN_BS>>>();
    scan2_kernel<<<1, 256>>>(n_edges);
    scan3_kernel<<<SCAN_NB, SCAN_BS>>>();
    scatter_kernel<<<grid_edge, TB>>>(rows, cols, vals, n_edges);

    // 3 propagation layers, acc += fused
    spmm_csr_kernel<<<grid_spmm, TB>>>((const float4*)cur,  (float4*)bufA, (float4*)acc);
    spmm_csr_kernel<<<grid_spmm, TB>>>((const float4*)bufA, (float4*)bufB, (float4*)acc);
    spmm_csr_kernel<<<grid_spmm, TB>>>((const float4*)bufB, (float4*)cur,  (float4*)acc);

    // scores
    const int grid_score = (batch + (TB / 32) - 1) / (TB / 32);
    score_kernel<<<grid_score, TB>>>(users, pos, neg, acc, out, batch);
}

// round 3
// speedup vs baseline: 2.8646x; 1.2730x over previous
#include <cuda_runtime.h>
#include <cuda_fp16.h>
#include <cstdint>

#define NUM_USERS 100000
#define NUM_ITEMS 50000
#define N_NODES   150000
#define EMB       64
#define BATCH     4096
#define MAX_EDGES 4800000

#define SCAN_BS   1024
#define SCAN_NB   ((N_NODES + SCAN_BS - 1) / SCAN_BS)   // 147

// ---- static scratch (allocation-free) ----
// fp16 propagation buffers: N_NODES * 64 halfs = N_NODES * 8 int4
__device__ int4  g_curH [(size_t)N_NODES * 8];
__device__ int4  g_bufAH[(size_t)N_NODES * 8];
__device__ int4  g_bufBH[(size_t)N_NODES * 8];
__device__ float g_acc  [(size_t)N_NODES * EMB];     // fp32 accumulator
__device__ int2  g_edges[MAX_EDGES];                 // {col, val_bits} sorted by row
__device__ int   g_count[N_NODES];
__device__ int   g_rowptr[N_NODES + 1];
__device__ int   g_off[N_NODES];
__device__ int   g_blocksum[SCAN_NB];
__device__ int   g_blockoff[SCAN_NB];

static __device__ __forceinline__ unsigned h2bits(__half2 h) {
    return *reinterpret_cast<unsigned*>(&h);
}

// ---------------------------------------------------------------------------
// init: curH = fp16(emb), acc = fp32(emb); zero row counters
// i indexes float4 chunks of the concatenated embedding (2 per int4-half chunk)
// ---------------------------------------------------------------------------
__global__ void init_kernel(const float4* __restrict__ uemb,
                            const float4* __restrict__ iemb,
                            uint2* __restrict__ curH,     // 4 halfs per uint2
                            float4* __restrict__ acc)
{
    const int n4      = N_NODES * (EMB / 4);      // 2,400,000 float4 chunks
    const int n4_user = NUM_USERS * (EMB / 4);
    int i = blockIdx.x * blockDim.x + threadIdx.x;
    if (i < N_NODES) g_count[i] = 0;
    if (i >= n4) return;
    float4 v = (i < n4_user) ? __ldg(uemb + i) : __ldg(iemb + i - n4_user);
    acc[i] = v;
    uint2 c;
    c.x = h2bits(__floats2half2_rn(v.x, v.y));
    c.y = h2bits(__floats2half2_rn(v.z, v.w));
    curH[i] = c;
}

// ---------------------------------------------------------------------------
// COO -> CSR: histogram, 3-step scan, scatter
// ---------------------------------------------------------------------------
__global__ void hist_kernel(const int* __restrict__ rows, int n)
{
    int i = blockIdx.x * blockDim.x + threadIdx.x;
    if (i < n) atomicAdd(&g_count[rows[i]], 1);
}

__global__ void scan1_kernel()   // per-block sums of g_count
{
    int idx = blockIdx.x * SCAN_BS + threadIdx.x;
    int c = (idx < N_NODES) ? g_count[idx] : 0;
    int lane = threadIdx.x & 31, wid = threadIdx.x >> 5;
    #pragma unroll
    for (int o = 16; o; o >>= 1) c += __shfl_down_sync(0xFFFFFFFFu, c, o);
    __shared__ int ws[32];
    if (lane == 0) ws[wid] = c;
    __syncthreads();
    if (wid == 0) {
        c = ws[lane];
        #pragma unroll
        for (int o = 16; o; o >>= 1) c += __shfl_down_sync(0xFFFFFFFFu, c, o);
        if (lane == 0) g_blocksum[blockIdx.x] = c;
    }
}

__global__ void scan2_kernel(int n_edges)  // exclusive scan of 147 block sums
{
    __shared__ int sh[SCAN_NB];
    int t = threadIdx.x;
    if (t < SCAN_NB) sh[t] = g_blocksum[t];
    __syncthreads();
    // Hillis-Steele inclusive scan
    for (int off = 1; off < SCAN_NB; off <<= 1) {
        int x = 0;
        if (t < SCAN_NB && t >= off) x = sh[t - off];
        __syncthreads();
        if (t < SCAN_NB) sh[t] += x;
        __syncthreads();
    }
    if (t < SCAN_NB) g_blockoff[t] = (t == 0) ? 0 : sh[t - 1];
    if (t == 0) g_rowptr[N_NODES] = n_edges;
}

__global__ void scan3_kernel()   // block-local exclusive scan + block offset
{
    int idx = blockIdx.x * SCAN_BS + threadIdx.x;
    int c = (idx < N_NODES) ? g_count[idx] : 0;
    int lane = threadIdx.x & 31, wid = threadIdx.x >> 5;
    int v = c;
    #pragma unroll
    for (int o = 1; o < 32; o <<= 1) {
        int t = __shfl_up_sync(0xFFFFFFFFu, v, o);
        if (lane >= o) v += t;
    }
    __shared__ int ws[32];
    if (lane == 31) ws[wid] = v;
    __syncthreads();
    if (wid == 0) {
        int orig = ws[lane];
        int s = orig;
        #pragma unroll
        for (int o = 1; o < 32; o <<= 1) {
            int t = __shfl_up_sync(0xFFFFFFFFu, s, o);
            if (lane >= o) s += t;
        }
        ws[lane] = s - orig;
    }
    __syncthreads();
    int excl = (v - c) + ws[wid] + g_blockoff[blockIdx.x];
    if (idx < N_NODES) { g_rowptr[idx] = excl; g_off[idx] = excl; }
}

__global__ void scatter_kernel(const int* __restrict__ rows,
                               const int* __restrict__ cols,
                               const float* __restrict__ vals, int n)
{
    int i = blockIdx.x * blockDim.x + threadIdx.x;
    if (i >= n) return;
    int row = rows[i];
    int pos = atomicAdd(&g_off[row], 1);
    g_edges[pos] = make_int2(cols[i], __float_as_int(vals[i]));
}

// ---------------------------------------------------------------------------
// CSR SpMM (fp16 src -> fp32 accum): 8 lanes per destination row.
// Each lane owns 8 features (one int4 = 8 halfs of the 128B row).
// dst = fp16(sum); acc += fp32 sum (exact layer contribution).
// ---------------------------------------------------------------------------
__global__ void spmm_csr_kernel(const int4* __restrict__ src,   // fp16 rows, 8 int4/row
                                int4* __restrict__ dst,         // fp16 rows
                                float4* __restrict__ acc)       // fp32, 16 float4/row
{
    int t = blockIdx.x * blockDim.x + threadIdx.x;
    int g = t >> 3;                 // destination row
    int l = t & 7;                  // feature slice (8 halfs)
    if (g >= N_NODES) return;
    unsigned gmask = 0xFFu << (threadIdx.x & 24);

    int start = __ldg(&g_rowptr[g]);
    int end   = __ldg(&g_rowptr[g + 1]);

    float4 alo = make_float4(0.f, 0.f, 0.f, 0.f);
    float4 ahi = make_float4(0.f, 0.f, 0.f, 0.f);

    int base = start;
    for (; base + 8 <= end; base += 8) {
        int2 e = __ldg(&g_edges[base + l]);
        #pragma unroll
        for (int k = 0; k < 8; k++) {
            int   col = __shfl_sync(gmask, e.x, k, 8);
            float v   = __int_as_float(__shfl_sync(gmask, e.y, k, 8));
            int4 q = __ldg(&src[(size_t)col * 8 + l]);
            float2 f0 = __half22float2(*reinterpret_cast<__half2*>(&q.x));
            float2 f1 = __half22float2(*reinterpret_cast<__half2*>(&q.y));
            float2 f2 = __half22float2(*reinterpret_cast<__half2*>(&q.z));
            float2 f3 = __half22float2(*reinterpret_cast<__half2*>(&q.w));
            alo.x = fmaf(v, f0.x, alo.x); alo.y = fmaf(v, f0.y, alo.y);
            alo.z = fmaf(v, f1.x, alo.z); alo.w = fmaf(v, f1.y, alo.w);
            ahi.x = fmaf(v, f2.x, ahi.x); ahi.y = fmaf(v, f2.y, ahi.y);
            ahi.z = fmaf(v, f3.x, ahi.z); ahi.w = fmaf(v, f3.y, ahi.w);
        }
    }
    int rem = end - base;
    if (rem > 0) {
        int2 e = (l < rem) ? __ldg(&g_edges[base + l]) : make_int2(0, 0);
        for (int k = 0; k < rem; k++) {
            int   col = __shfl_sync(gmask, e.x, k, 8);
            float v   = __int_as_float(__shfl_sync(gmask, e.y, k, 8));
            int4 q = __ldg(&src[(size_t)col * 8 + l]);
            float2 f0 = __half22float2(*reinterpret_cast<__half2*>(&q.x));
            float2 f1 = __half22float2(*reinterpret_cast<__half2*>(&q.y));
            float2 f2 = __half22float2(*reinterpret_cast<__half2*>(&q.z));
            float2 f3 = __half22float2(*reinterpret_cast<__half2*>(&q.w));
            alo.x = fmaf(v, f0.x, alo.x); alo.y = fmaf(v, f0.y, alo.y);
            alo.z = fmaf(v, f1.x, alo.z); alo.w = fmaf(v, f1.y, alo.w);
            ahi.x = fmaf(v, f2.x, ahi.x); ahi.y = fmaf(v, f2.y, ahi.y);
            ahi.z = fmaf(v, f3.x, ahi.z); ahi.w = fmaf(v, f3.y, ahi.w);
        }
    }

    // fp16 dst for next layer
    int4 o;
    o.x = h2bits(__floats2half2_rn(alo.x, alo.y));
    o.y = h2bits(__floats2half2_rn(alo.z, alo.w));
    o.z = h2bits(__floats2half2_rn(ahi.x, ahi.y));
    o.w = h2bits(__floats2half2_rn(ahi.z, ahi.w));
    dst[(size_t)g * 8 + l] = o;

    // fp32 acc += (exact contribution)
    size_t ai = (size_t)g * 16 + (size_t)l * 2;
    float4 c0 = acc[ai];
    c0.x += alo.x; c0.y += alo.y; c0.z += alo.z; c0.w += alo.w;
    acc[ai] = c0;
    float4 c1 = acc[ai + 1];
    c1.x += ahi.x; c1.y += ahi.y; c1.z += ahi.z; c1.w += ahi.w;
    acc[ai + 1] = c1;
}

// ---------------------------------------------------------------------------
// scoring: one warp per batch element (fp32 acc); score = dot(acc_u,acc_i)/16
// ---------------------------------------------------------------------------
__global__ void score_kernel(const int* __restrict__ users,
                             const int* __restrict__ pos_items,
                             const int* __restrict__ neg_items,
                             const float* __restrict__ acc,
                             float* __restrict__ out,
                             int batch)
{
    int w = (blockIdx.x * blockDim.x + threadIdx.x) >> 5;
    int l = threadIdx.x & 31;
    if (w >= batch) return;

    int urow = __ldg(users + w);
    int prow = NUM_USERS + __ldg(pos_items + w);
    int nrow = NUM_USERS + __ldg(neg_items + w);

    const float2* base = reinterpret_cast<const float2*>(acc);
    float2 u = __ldg(base + (size_t)urow * (EMB / 2) + l);
    float2 p = __ldg(base + (size_t)prow * (EMB / 2) + l);
    float2 q = __ldg(base + (size_t)nrow * (EMB / 2) + l);

    float ps = u.x * p.x + u.y * p.y;
    float ns = u.x * q.x + u.y * q.y;
    #pragma unroll
    for (int o = 16; o; o >>= 1) {
        ps += __shfl_xor_sync(0xFFFFFFFFu, ps, o);
        ns += __shfl_xor_sync(0xFFFFFFFFu, ns, o);
    }
    if (l == 0) {
        out[w]         = ps * (1.0f / 16.0f);
        out[batch + w] = ns * (1.0f / 16.0f);
    }
}

// ---------------------------------------------------------------------------
extern "C" void kernel_launch(void* const* d_in, const int* in_sizes, int n_in,
                              void* d_out, int out_size)
{
    const int*   users = (const int*)  d_in[0];
    const int*   pos   = (const int*)  d_in[1];
    const int*   neg   = (const int*)  d_in[2];
    const int*   rows  = (const int*)  d_in[3];
    const int*   cols  = (const int*)  d_in[4];
    const float* vals  = (const float*)d_in[5];
    const float* uemb  = (const float*)d_in[6];
    const float* iemb  = (const float*)d_in[7];
    float* out = (float*)d_out;

    const int n_edges = in_sizes[3];
    const int batch   = in_sizes[0];

    int4 *curH, *bufAH, *bufBH;
    float *acc;
    cudaGetSymbolAddress((void**)&curH,  g_curH);
    cudaGetSymbolAddress((void**)&bufAH, g_bufAH);
    cudaGetSymbolAddress((void**)&bufBH, g_bufBH);
    cudaGetSymbolAddress((void**)&acc,   g_acc);

    const int n4 = N_NODES * (EMB / 4);
    const int TB = 256;
    const int grid_n4   = (n4 + TB - 1) / TB;
    const int grid_edge = (n_edges + TB - 1) / TB;
    const int grid_spmm = (N_NODES * 8 + TB - 1) / TB;

    // emb -> curH (fp16), acc (fp32); zero counters
    init_kernel<<<grid_n4, TB>>>((const float4*)uemb, (const float4*)iemb,
                                 (uint2*)curH, (float4*)acc);

    // COO -> CSR
    hist_kernel<<<grid_edge, TB>>>(rows, n_edges);
    scan1_kernel<<<SCAN_NB, SCAN_BS>>>();
    scan2_kernel<<<1, 256>>>(n_edges);
    scan3_kernel<<<SCAN_NB, SCAN_BS>>>();
    scatter_kernel<<<grid_edge, TB>>>(rows, cols, vals, n_edges);

    // 3 propagation layers (fp16 state, fp32 acc+=)
    spmm_csr_kernel<<<grid_spmm, TB>>>(curH,  bufAH, (float4*)acc);
    spmm_csr_kernel<<<grid_spmm, TB>>>(bufAH, bufBH, (float4*)acc);
    spmm_csr_kernel<<<grid_spmm, TB>>>(bufBH, curH,  (float4*)acc);

    // scores
    const int grid_score = (batch + (TB / 32) - 1) / (TB / 32);
    score_kernel<<<grid_score, TB>>>(users, pos, neg, acc, out, batch);
}